// round 12
// baseline (speedup 1.0000x reference)
#include <cuda_runtime.h>

// EMA with bias correction — R5 shape, write-back stores (cache-policy A/B).
// x: (32, 256, 8192) f32 -> 8192 rows of T=8192.
// y[t] = 0.99*y[t-1] + 0.01*x[t];  out[t] = y[t] / (1 - 0.99^(t+1))
//
// Block = row (512 thr, 16 warps). Warp w owns elements [w*512, (w+1)*512).
// Lane l holds 4 groups of 4 contiguous floats at i*128 + l*4 (i=0..3)
// -> every LDG.128 / STG.128 warp-coalesced; all loads front-batched.
// Loads: .cs (no reuse, avoid L2 pollution). Stores: default write-back so
// the 126MB L2 can aggregate dirty lines into large DRAM write bursts,
// reducing read<->write bus turnaround on the 1:1 mixed stream.
//
// Bias correction: t >= 2048 -> 0.99^(t+1) < 2^-25, fp32 corr == 1.0 exactly
// (warps 4..15 skip it). Warps 0-3 compute corr inline from exact constant
// products + MUFU reciprocal (hidden under memory latency).

#define T_LEN   8192
#define THREADS 512
#define NWARP   (THREADS / 32)   // 16
#define SEG     (T_LEN / NWARP)  // 512 elems per warp
#define NBLK    (SEG / 128)      // 4 blocks of 128 per warp

__global__ __launch_bounds__(THREADS, 3)
void ema_kernel(const float* __restrict__ x, float* __restrict__ out) {
    const int lane = threadIdx.x & 31;
    const int warp = threadIdx.x >> 5;
    const int row  = blockIdx.x;

    const float OM = 0.99f;
    const float M  = 0.01f;

    // Compile-time decay constants
    const float A4_1  = OM * OM * OM * OM;    // 0.99^4
    const float A4_2  = A4_1  * A4_1;         // 0.99^8
    const float A4_4  = A4_2  * A4_2;         // 0.99^16
    const float A4_8  = A4_4  * A4_4;         // 0.99^32
    const float A4_16 = A4_8  * A4_8;         // 0.99^64
    const float A128  = A4_16 * A4_16;        // 0.99^128
    const float A256  = A128  * A128;         // 0.99^256
    const float A512  = A256  * A256;         // 0.99^512

    // Base: this lane's first group within its warp's 512-element segment
    const size_t base = (size_t)row * T_LEN + (size_t)warp * SEG + (size_t)lane * 4;
    const float4* __restrict__ p = (const float4*)(x + base);

    // Coalesced streaming loads: block i at +i*128 floats (= +32 float4)
    float4 v[NBLK];
#pragma unroll
    for (int i = 0; i < NBLK; i++) v[i] = __ldcs(p + i * 32);

    // Level 1 + 2: per-block serial affine over 4 elems, then b-only
    // warp Kogge-Stone (decay per lane is uniform A4, so only b scans).
    float excl[NBLK], b128[NBLK];
#pragma unroll
    for (int i = 0; i < NBLK; i++) {
        float b;
        b = M * v[i].x;
        b = fmaf(OM, b, M * v[i].y);
        b = fmaf(OM, b, M * v[i].z);
        b = fmaf(OM, b, M * v[i].w);

        float t1 = __shfl_up_sync(0xffffffffu, b, 1);
        if (lane >= 1)  b = fmaf(A4_1,  t1, b);
        float t2 = __shfl_up_sync(0xffffffffu, b, 2);
        if (lane >= 2)  b = fmaf(A4_2,  t2, b);
        float t4 = __shfl_up_sync(0xffffffffu, b, 4);
        if (lane >= 4)  b = fmaf(A4_4,  t4, b);
        float t8 = __shfl_up_sync(0xffffffffu, b, 8);
        if (lane >= 8)  b = fmaf(A4_8,  t8, b);
        float t16 = __shfl_up_sync(0xffffffffu, b, 16);
        if (lane >= 16) b = fmaf(A4_16, t16, b);

        float e = __shfl_up_sync(0xffffffffu, b, 1);
        excl[i] = (lane == 0) ? 0.0f : e;          // carry into lane l, block i
        b128[i] = __shfl_sync(0xffffffffu, b, 31); // block-i total
    }

    // Warp total over its 512 elements: chain the 4 block totals
    float tot = b128[0];
#pragma unroll
    for (int i = 1; i < NBLK; i++) tot = fmaf(A128, tot, b128[i]);

    __shared__ float wsum[NWARP];
    if (lane == 0) wsum[warp] = tot;
    __syncthreads();

    // Carry into this warp: ordered combine of prior warp totals
    float cw = 0.0f;
#pragma unroll
    for (int j = 0; j < NWARP; j++) {
        if (j < warp) cw = fmaf(A512, cw, wsum[j]);
    }

    // Lane decay 0.99^(4*lane) via binary products of constants
    float al = (lane & 1) ? A4_1 : 1.0f;
    if (lane & 2)  al *= A4_2;
    if (lane & 4)  al *= A4_4;
    if (lane & 8)  al *= A4_8;
    if (lane & 16) al *= A4_16;

    float4* __restrict__ po = (float4*)(out + base);

    if (warp < 4) {
        // global t = warp*512 + i*128 + lane*4 + j < 2048: apply correction.
        // q at this lane's (i=0, j=0) element: 0.99^(warp*512 + lane*4 + 1)
        float qb = OM * al;
        if (warp & 1) qb *= A512;
        if (warp & 2) qb *= A512 * A512;

        float c = cw;  // EMA state at block-i start (lane 0 position)
#pragma unroll
        for (int i = 0; i < NBLK; i++) {
            float cc = fmaf(al, c, excl[i]);   // carry into this lane's group
            float q = qb;
            float4 w;
            cc = fmaf(OM, cc, M * v[i].x); w.x = __fdividef(cc, 1.0f - q); q *= OM;
            cc = fmaf(OM, cc, M * v[i].y); w.y = __fdividef(cc, 1.0f - q); q *= OM;
            cc = fmaf(OM, cc, M * v[i].z); w.z = __fdividef(cc, 1.0f - q); q *= OM;
            cc = fmaf(OM, cc, M * v[i].w); w.w = __fdividef(cc, 1.0f - q);
            po[i * 32] = w;                    // write-back store
            c  = fmaf(A128, c, b128[i]);       // state at next block start
            qb *= A128;
        }
    } else {
        // t >= 2048: 0.99^(t+1) < 2^-25 -> fp32 corr == 1.0 exactly
        float c = cw;
#pragma unroll
        for (int i = 0; i < NBLK; i++) {
            float cc = fmaf(al, c, excl[i]);
            float4 w;
            cc = fmaf(OM, cc, M * v[i].x); w.x = cc;
            cc = fmaf(OM, cc, M * v[i].y); w.y = cc;
            cc = fmaf(OM, cc, M * v[i].z); w.z = cc;
            cc = fmaf(OM, cc, M * v[i].w); w.w = cc;
            po[i * 32] = w;                    // write-back store
            c = fmaf(A128, c, b128[i]);
        }
    }
}

extern "C" void kernel_launch(void* const* d_in, const int* in_sizes, int n_in,
                              void* d_out, int out_size) {
    const float* x = (const float*)d_in[0];
    float* out = (float*)d_out;

    int rows = in_sizes[0] / T_LEN;   // 8192

    ema_kernel<<<rows, THREADS>>>(x, out);
}

// round 13
// speedup vs baseline: 1.0055x; 1.0055x over previous
#include <cuda_runtime.h>

// EMA with bias correction — FINAL kernel.
// x: (32, 256, 8192) f32 -> 8192 rows of T=8192.
// y[t] = 0.99*y[t-1] + 0.01*x[t];  out[t] = y[t] / (1 - 0.99^(t+1))
//
// Block = row (512 thr, 16 warps). Warp w owns elements [w*512, (w+1)*512).
// Lane l holds 4 groups of 4 contiguous floats at i*128 + l*4 (i=0..3)
// -> every LDG.128 / STG.128 warp-coalesced; all loads front-batched.
// One-shot launch (grid = 8192 rows): phase-staggered CTAs keep the DRAM
// read stream continuous. A/B-tested and rejected: persistent grid-stride,
// explicit register prefetch, write-back stores, 1/2/4 rows per CTA,
// occupancy 44-74%. Converged at the mixed 1:1 r/w HBM3e ceiling:
// ~7.2 TB/s combined (~90% of spec), DRAM-active ~80%.
//
// Bias correction: t >= 2048 -> 0.99^(t+1) < 2^-25, fp32 corr == 1.0 exactly
// (warps 4..15 skip it). Warps 0-3 compute corr inline from exact constant
// products + MUFU reciprocal (hidden under memory latency).

#define T_LEN   8192
#define THREADS 512
#define NWARP   (THREADS / 32)   // 16
#define SEG     (T_LEN / NWARP)  // 512 elems per warp
#define NBLK    (SEG / 128)      // 4 blocks of 128 per warp

__global__ __launch_bounds__(THREADS, 3)
void ema_kernel(const float* __restrict__ x, float* __restrict__ out) {
    const int lane = threadIdx.x & 31;
    const int warp = threadIdx.x >> 5;
    const int row  = blockIdx.x;

    const float OM = 0.99f;
    const float M  = 0.01f;

    // Compile-time decay constants
    const float A4_1  = OM * OM * OM * OM;    // 0.99^4
    const float A4_2  = A4_1  * A4_1;         // 0.99^8
    const float A4_4  = A4_2  * A4_2;         // 0.99^16
    const float A4_8  = A4_4  * A4_4;         // 0.99^32
    const float A4_16 = A4_8  * A4_8;         // 0.99^64
    const float A128  = A4_16 * A4_16;        // 0.99^128
    const float A256  = A128  * A128;         // 0.99^256
    const float A512  = A256  * A256;         // 0.99^512

    // Base: this lane's first group within its warp's 512-element segment
    const size_t base = (size_t)row * T_LEN + (size_t)warp * SEG + (size_t)lane * 4;
    const float4* __restrict__ p = (const float4*)(x + base);

    // Coalesced streaming loads: block i at +i*128 floats (= +32 float4)
    float4 v[NBLK];
#pragma unroll
    for (int i = 0; i < NBLK; i++) v[i] = __ldcs(p + i * 32);

    // Level 1 + 2: per-block serial affine over 4 elems, then b-only
    // warp Kogge-Stone (decay per lane is uniform A4, so only b scans).
    float excl[NBLK], b128[NBLK];
#pragma unroll
    for (int i = 0; i < NBLK; i++) {
        float b;
        b = M * v[i].x;
        b = fmaf(OM, b, M * v[i].y);
        b = fmaf(OM, b, M * v[i].z);
        b = fmaf(OM, b, M * v[i].w);

        float t1 = __shfl_up_sync(0xffffffffu, b, 1);
        if (lane >= 1)  b = fmaf(A4_1,  t1, b);
        float t2 = __shfl_up_sync(0xffffffffu, b, 2);
        if (lane >= 2)  b = fmaf(A4_2,  t2, b);
        float t4 = __shfl_up_sync(0xffffffffu, b, 4);
        if (lane >= 4)  b = fmaf(A4_4,  t4, b);
        float t8 = __shfl_up_sync(0xffffffffu, b, 8);
        if (lane >= 8)  b = fmaf(A4_8,  t8, b);
        float t16 = __shfl_up_sync(0xffffffffu, b, 16);
        if (lane >= 16) b = fmaf(A4_16, t16, b);

        float e = __shfl_up_sync(0xffffffffu, b, 1);
        excl[i] = (lane == 0) ? 0.0f : e;          // carry into lane l, block i
        b128[i] = __shfl_sync(0xffffffffu, b, 31); // block-i total
    }

    // Warp total over its 512 elements: chain the 4 block totals
    float tot = b128[0];
#pragma unroll
    for (int i = 1; i < NBLK; i++) tot = fmaf(A128, tot, b128[i]);

    __shared__ float wsum[NWARP];
    if (lane == 0) wsum[warp] = tot;
    __syncthreads();

    // Carry into this warp: ordered combine of prior warp totals
    float cw = 0.0f;
#pragma unroll
    for (int j = 0; j < NWARP; j++) {
        if (j < warp) cw = fmaf(A512, cw, wsum[j]);
    }

    // Lane decay 0.99^(4*lane) via binary products of constants
    float al = (lane & 1) ? A4_1 : 1.0f;
    if (lane & 2)  al *= A4_2;
    if (lane & 4)  al *= A4_4;
    if (lane & 8)  al *= A4_8;
    if (lane & 16) al *= A4_16;

    float4* __restrict__ po = (float4*)(out + base);

    if (warp < 4) {
        // global t = warp*512 + i*128 + lane*4 + j < 2048: apply correction.
        // q at this lane's (i=0, j=0) element: 0.99^(warp*512 + lane*4 + 1)
        float qb = OM * al;
        if (warp & 1) qb *= A512;
        if (warp & 2) qb *= A512 * A512;

        float c = cw;  // EMA state at block-i start (lane 0 position)
#pragma unroll
        for (int i = 0; i < NBLK; i++) {
            float cc = fmaf(al, c, excl[i]);   // carry into this lane's group
            float q = qb;
            float4 w;
            cc = fmaf(OM, cc, M * v[i].x); w.x = __fdividef(cc, 1.0f - q); q *= OM;
            cc = fmaf(OM, cc, M * v[i].y); w.y = __fdividef(cc, 1.0f - q); q *= OM;
            cc = fmaf(OM, cc, M * v[i].z); w.z = __fdividef(cc, 1.0f - q); q *= OM;
            cc = fmaf(OM, cc, M * v[i].w); w.w = __fdividef(cc, 1.0f - q);
            __stcs(po + i * 32, w);
            c  = fmaf(A128, c, b128[i]);       // state at next block start
            qb *= A128;
        }
    } else {
        // t >= 2048: 0.99^(t+1) < 2^-25 -> fp32 corr == 1.0 exactly
        float c = cw;
#pragma unroll
        for (int i = 0; i < NBLK; i++) {
            float cc = fmaf(al, c, excl[i]);
            float4 w;
            cc = fmaf(OM, cc, M * v[i].x); w.x = cc;
            cc = fmaf(OM, cc, M * v[i].y); w.y = cc;
            cc = fmaf(OM, cc, M * v[i].z); w.z = cc;
            cc = fmaf(OM, cc, M * v[i].w); w.w = cc;
            __stcs(po + i * 32, w);
            c = fmaf(A128, c, b128[i]);
        }
    }
}

extern "C" void kernel_launch(void* const* d_in, const int* in_sizes, int n_in,
                              void* d_out, int out_size) {
    const float* x = (const float*)d_in[0];
    float* out = (float*)d_out;

    int rows = in_sizes[0] / T_LEN;   // 8192

    ema_kernel<<<rows, THREADS>>>(x, out);
}

// round 14
// speedup vs baseline: 1.0214x; 1.0159x over previous
#include <cuda_runtime.h>

// EMA with bias correction — FINAL kernel (converged, session closed).
// x: (32, 256, 8192) f32 -> 8192 rows of T=8192.
// y[t] = 0.99*y[t-1] + 0.01*x[t];  out[t] = y[t] / (1 - 0.99^(t+1))
//
// Block = row (512 thr, 16 warps). Warp w owns elements [w*512, (w+1)*512).
// Lane l holds 4 groups of 4 contiguous floats at i*128 + l*4 (i=0..3)
// -> every LDG.128 / STG.128 warp-coalesced; all loads front-batched.
// One-shot launch (grid = 8192 rows): phase-staggered CTAs keep the DRAM
// read stream continuous. A/B-tested and rejected: persistent grid-stride,
// explicit register prefetch, write-back stores, 1/2/4 rows per CTA,
// occupancy 44-74%. Converged at the mixed 1:1 r/w HBM3e ceiling:
// ~7.2 TB/s combined (~90% of spec), DRAM-active ~80%.
//
// Bias correction: t >= 2048 -> 0.99^(t+1) < 2^-25, fp32 corr == 1.0 exactly
// (warps 4..15 skip it). Warps 0-3 compute corr inline from exact constant
// products + MUFU reciprocal (hidden under memory latency).

#define T_LEN   8192
#define THREADS 512
#define NWARP   (THREADS / 32)   // 16
#define SEG     (T_LEN / NWARP)  // 512 elems per warp
#define NBLK    (SEG / 128)      // 4 blocks of 128 per warp

__global__ __launch_bounds__(THREADS, 3)
void ema_kernel(const float* __restrict__ x, float* __restrict__ out) {
    const int lane = threadIdx.x & 31;
    const int warp = threadIdx.x >> 5;
    const int row  = blockIdx.x;

    const float OM = 0.99f;
    const float M  = 0.01f;

    // Compile-time decay constants
    const float A4_1  = OM * OM * OM * OM;    // 0.99^4
    const float A4_2  = A4_1  * A4_1;         // 0.99^8
    const float A4_4  = A4_2  * A4_2;         // 0.99^16
    const float A4_8  = A4_4  * A4_4;         // 0.99^32
    const float A4_16 = A4_8  * A4_8;         // 0.99^64
    const float A128  = A4_16 * A4_16;        // 0.99^128
    const float A256  = A128  * A128;         // 0.99^256
    const float A512  = A256  * A256;         // 0.99^512

    // Base: this lane's first group within its warp's 512-element segment
    const size_t base = (size_t)row * T_LEN + (size_t)warp * SEG + (size_t)lane * 4;
    const float4* __restrict__ p = (const float4*)(x + base);

    // Coalesced streaming loads: block i at +i*128 floats (= +32 float4)
    float4 v[NBLK];
#pragma unroll
    for (int i = 0; i < NBLK; i++) v[i] = __ldcs(p + i * 32);

    // Level 1 + 2: per-block serial affine over 4 elems, then b-only
    // warp Kogge-Stone (decay per lane is uniform A4, so only b scans).
    float excl[NBLK], b128[NBLK];
#pragma unroll
    for (int i = 0; i < NBLK; i++) {
        float b;
        b = M * v[i].x;
        b = fmaf(OM, b, M * v[i].y);
        b = fmaf(OM, b, M * v[i].z);
        b = fmaf(OM, b, M * v[i].w);

        float t1 = __shfl_up_sync(0xffffffffu, b, 1);
        if (lane >= 1)  b = fmaf(A4_1,  t1, b);
        float t2 = __shfl_up_sync(0xffffffffu, b, 2);
        if (lane >= 2)  b = fmaf(A4_2,  t2, b);
        float t4 = __shfl_up_sync(0xffffffffu, b, 4);
        if (lane >= 4)  b = fmaf(A4_4,  t4, b);
        float t8 = __shfl_up_sync(0xffffffffu, b, 8);
        if (lane >= 8)  b = fmaf(A4_8,  t8, b);
        float t16 = __shfl_up_sync(0xffffffffu, b, 16);
        if (lane >= 16) b = fmaf(A4_16, t16, b);

        float e = __shfl_up_sync(0xffffffffu, b, 1);
        excl[i] = (lane == 0) ? 0.0f : e;          // carry into lane l, block i
        b128[i] = __shfl_sync(0xffffffffu, b, 31); // block-i total
    }

    // Warp total over its 512 elements: chain the 4 block totals
    float tot = b128[0];
#pragma unroll
    for (int i = 1; i < NBLK; i++) tot = fmaf(A128, tot, b128[i]);

    __shared__ float wsum[NWARP];
    if (lane == 0) wsum[warp] = tot;
    __syncthreads();

    // Carry into this warp: ordered combine of prior warp totals
    float cw = 0.0f;
#pragma unroll
    for (int j = 0; j < NWARP; j++) {
        if (j < warp) cw = fmaf(A512, cw, wsum[j]);
    }

    // Lane decay 0.99^(4*lane) via binary products of constants
    float al = (lane & 1) ? A4_1 : 1.0f;
    if (lane & 2)  al *= A4_2;
    if (lane & 4)  al *= A4_4;
    if (lane & 8)  al *= A4_8;
    if (lane & 16) al *= A4_16;

    float4* __restrict__ po = (float4*)(out + base);

    if (warp < 4) {
        // global t = warp*512 + i*128 + lane*4 + j < 2048: apply correction.
        // q at this lane's (i=0, j=0) element: 0.99^(warp*512 + lane*4 + 1)
        float qb = OM * al;
        if (warp & 1) qb *= A512;
        if (warp & 2) qb *= A512 * A512;

        float c = cw;  // EMA state at block-i start (lane 0 position)
#pragma unroll
        for (int i = 0; i < NBLK; i++) {
            float cc = fmaf(al, c, excl[i]);   // carry into this lane's group
            float q = qb;
            float4 w;
            cc = fmaf(OM, cc, M * v[i].x); w.x = __fdividef(cc, 1.0f - q); q *= OM;
            cc = fmaf(OM, cc, M * v[i].y); w.y = __fdividef(cc, 1.0f - q); q *= OM;
            cc = fmaf(OM, cc, M * v[i].z); w.z = __fdividef(cc, 1.0f - q); q *= OM;
            cc = fmaf(OM, cc, M * v[i].w); w.w = __fdividef(cc, 1.0f - q);
            __stcs(po + i * 32, w);
            c  = fmaf(A128, c, b128[i]);       // state at next block start
            qb *= A128;
        }
    } else {
        // t >= 2048: 0.99^(t+1) < 2^-25 -> fp32 corr == 1.0 exactly
        float c = cw;
#pragma unroll
        for (int i = 0; i < NBLK; i++) {
            float cc = fmaf(al, c, excl[i]);
            float4 w;
            cc = fmaf(OM, cc, M * v[i].x); w.x = cc;
            cc = fmaf(OM, cc, M * v[i].y); w.y = cc;
            cc = fmaf(OM, cc, M * v[i].z); w.z = cc;
            cc = fmaf(OM, cc, M * v[i].w); w.w = cc;
            __stcs(po + i * 32, w);
            c = fmaf(A128, c, b128[i]);
        }
    }
}

extern "C" void kernel_launch(void* const* d_in, const int* in_sizes, int n_in,
                              void* d_out, int out_size) {
    const float* x = (const float*)d_in[0];
    float* out = (float*)d_out;

    int rows = in_sizes[0] / T_LEN;   // 8192

    ema_kernel<<<rows, THREADS>>>(x, out);
}